// round 7
// baseline (speedup 1.0000x reference)
#include <cuda_runtime.h>
#include <math.h>

// Problem constants
#define EMBED 2048
#define NB    2
#define LSEQ  2048
#define HEADS 16
#define HDIM  128
#define MROWS (NB * LSEQ)          // 4096 rows in the flattened [N*L, E] view

// ---------------------------------------------------------------------------
// Scratch: __device__ globals (allocation inside kernel_launch is forbidden)
// ---------------------------------------------------------------------------
__device__ float g_q[(size_t)MROWS * EMBED];
__device__ float g_k[(size_t)MROWS * EMBED];
__device__ float g_v[(size_t)MROWS * EMBED];
__device__ float g_attn[(size_t)MROWS * EMBED];

// ---------------------------------------------------------------------------
// SGEMM (NT): C[m,n] = sum_k A[m,k] * B[n,k] (+ bias[n])
// A: [M,K] row-major, B: [N,K] row-major (i.e. computes A @ B^T)
// 128x128 block tile, BK=16, 256 threads, 8x8 per thread.
// Double-buffered SMEM (2 stages) + register prefetch: one barrier per K-step.
// ---------------------------------------------------------------------------
constexpr int BM = 128;
constexpr int BN = 128;
constexpr int BK = 16;

__global__ __launch_bounds__(256) void sgemm_nt(
    const float* __restrict__ A, const float* __restrict__ B,
    const float* __restrict__ bias, float* __restrict__ C,
    int M, int N, int K)
{
    __shared__ float As[2][BK][BM];   // transposed: As[buf][k][m]
    __shared__ float Bs[2][BK][BN];   // transposed: Bs[buf][k][n]

    const int tid = threadIdx.x;
    const int bm  = blockIdx.y * BM;
    const int bn  = blockIdx.x * BN;
    const int tx  = tid & 15;      // N direction (8 cols each)
    const int ty  = tid >> 4;      // M direction (8 rows each)

    // Each thread loads 8 consecutive K-floats of one tile row (2x float4)
    const int lr = tid >> 1;           // tile row 0..127
    const int lk = (tid & 1) * 8;      // k offset 0 or 8

    const float* aPtr = A + (size_t)(bm + lr) * K + lk;
    const float* bPtr = B + (size_t)(bn + lr) * K + lk;

    // Prefetch tile 0 into registers, commit to buffer 0
    float4 pa0 = *(const float4*)(aPtr);
    float4 pa1 = *(const float4*)(aPtr + 4);
    float4 pb0 = *(const float4*)(bPtr);
    float4 pb1 = *(const float4*)(bPtr + 4);

    As[0][lk + 0][lr] = pa0.x; As[0][lk + 1][lr] = pa0.y;
    As[0][lk + 2][lr] = pa0.z; As[0][lk + 3][lr] = pa0.w;
    As[0][lk + 4][lr] = pa1.x; As[0][lk + 5][lr] = pa1.y;
    As[0][lk + 6][lr] = pa1.z; As[0][lk + 7][lr] = pa1.w;
    Bs[0][lk + 0][lr] = pb0.x; Bs[0][lk + 1][lr] = pb0.y;
    Bs[0][lk + 2][lr] = pb0.z; Bs[0][lk + 3][lr] = pb0.w;
    Bs[0][lk + 4][lr] = pb1.x; Bs[0][lk + 5][lr] = pb1.y;
    Bs[0][lk + 6][lr] = pb1.z; Bs[0][lk + 7][lr] = pb1.w;
    __syncthreads();

    float acc[8][8];
    #pragma unroll
    for (int i = 0; i < 8; i++)
        #pragma unroll
        for (int j = 0; j < 8; j++) acc[i][j] = 0.f;

    const int ntiles = K / BK;
    for (int t = 0; t < ntiles; t++) {
        const int cur = t & 1;
        const int nxt = cur ^ 1;
        const bool has_next = (t + 1 < ntiles);

        // prefetch next tile into registers (lands while we do 2048 FFMAs)
        if (has_next) {
            const float* ap = aPtr + (size_t)(t + 1) * BK;
            const float* bp = bPtr + (size_t)(t + 1) * BK;
            pa0 = *(const float4*)(ap);
            pa1 = *(const float4*)(ap + 4);
            pb0 = *(const float4*)(bp);
            pb1 = *(const float4*)(bp + 4);
        }

        #pragma unroll
        for (int k = 0; k < BK; k++) {
            float4 a0 = *(const float4*)&As[cur][k][ty * 8];
            float4 a1 = *(const float4*)&As[cur][k][ty * 8 + 4];
            float4 b0 = *(const float4*)&Bs[cur][k][tx * 8];
            float4 b1 = *(const float4*)&Bs[cur][k][tx * 8 + 4];
            float ra[8] = {a0.x, a0.y, a0.z, a0.w, a1.x, a1.y, a1.z, a1.w};
            float rb[8] = {b0.x, b0.y, b0.z, b0.w, b1.x, b1.y, b1.z, b1.w};
            #pragma unroll
            for (int i = 0; i < 8; i++)
                #pragma unroll
                for (int j = 0; j < 8; j++)
                    acc[i][j] = fmaf(ra[i], rb[j], acc[i][j]);
        }

        // commit prefetched tile into the OTHER buffer; single barrier per step
        if (has_next) {
            As[nxt][lk + 0][lr] = pa0.x; As[nxt][lk + 1][lr] = pa0.y;
            As[nxt][lk + 2][lr] = pa0.z; As[nxt][lk + 3][lr] = pa0.w;
            As[nxt][lk + 4][lr] = pa1.x; As[nxt][lk + 5][lr] = pa1.y;
            As[nxt][lk + 6][lr] = pa1.z; As[nxt][lk + 7][lr] = pa1.w;
            Bs[nxt][lk + 0][lr] = pb0.x; Bs[nxt][lk + 1][lr] = pb0.y;
            Bs[nxt][lk + 2][lr] = pb0.z; Bs[nxt][lk + 3][lr] = pb0.w;
            Bs[nxt][lk + 4][lr] = pb1.x; Bs[nxt][lk + 5][lr] = pb1.y;
            Bs[nxt][lk + 6][lr] = pb1.z; Bs[nxt][lk + 7][lr] = pb1.w;
            __syncthreads();
        }
    }

    // epilogue (+ optional bias), vectorized stores
    float bj[8];
    if (bias) {
        float4 v0 = *(const float4*)(bias + bn + tx * 8);
        float4 v1 = *(const float4*)(bias + bn + tx * 8 + 4);
        bj[0] = v0.x; bj[1] = v0.y; bj[2] = v0.z; bj[3] = v0.w;
        bj[4] = v1.x; bj[5] = v1.y; bj[6] = v1.z; bj[7] = v1.w;
    } else {
        #pragma unroll
        for (int j = 0; j < 8; j++) bj[j] = 0.f;
    }

    #pragma unroll
    for (int i = 0; i < 8; i++) {
        const int gr = bm + ty * 8 + i;
        float* cp = C + (size_t)gr * N + bn + tx * 8;
        float4 o0, o1;
        o0.x = acc[i][0] + bj[0]; o0.y = acc[i][1] + bj[1];
        o0.z = acc[i][2] + bj[2]; o0.w = acc[i][3] + bj[3];
        o1.x = acc[i][4] + bj[4]; o1.y = acc[i][5] + bj[5];
        o1.z = acc[i][6] + bj[6]; o1.w = acc[i][7] + bj[7];
        *(float4*)(cp)     = o0;
        *(float4*)(cp + 4) = o1;
    }
}

// ---------------------------------------------------------------------------
// Per-position head-mixing attention.
// The reference einsum's t,s index HEADS and h indexes sequence, so for each
// (b,l): Qr,Kr,Vr = [16,128] head matrices at that position.
//   E = Qr @ Kr^T / sqrt(128)  (16x16), row softmax, O = A @ Vr (16x128)
// Output written back flattened [N*L, 2048] (layout matches final reshape).
// One block per position, 256 threads.
// ---------------------------------------------------------------------------
__global__ __launch_bounds__(256) void attn_kernel(
    const float* __restrict__ Q, const float* __restrict__ K,
    const float* __restrict__ V, float* __restrict__ O)
{
    __shared__ float q_s[16][132];   // pad 132: 16B-aligned rows, no stride-128 conflicts
    __shared__ float k_s[16][132];
    __shared__ float v_s[16][132];
    __shared__ float e_s[16][17];

    const int row = blockIdx.x;                 // b*L + l
    const int tid = threadIdx.x;
    const size_t base = (size_t)row * EMBED;

    // Load Q/K/V rows: 512 float4 per matrix, 2 per thread
    #pragma unroll
    for (int i = 0; i < 2; i++) {
        const int idx = tid + i * 256;          // float4 index 0..511
        const int h = idx >> 5;                 // head 0..15
        const int d = (idx & 31) * 4;           // dim offset
        const size_t g = base + (size_t)h * HDIM + d;
        *(float4*)&q_s[h][d] = *(const float4*)(Q + g);
        *(float4*)&k_s[h][d] = *(const float4*)(K + g);
        *(float4*)&v_s[h][d] = *(const float4*)(V + g);
    }
    __syncthreads();

    // Energy: thread (ei,ej) computes one of the 256 entries
    {
        const int ei = tid >> 4, ej = tid & 15;
        float e = 0.f;
        #pragma unroll
        for (int d = 0; d < HDIM; d++)
            e = fmaf(q_s[ei][d], k_s[ej][d], e);
        e_s[ei][ej] = e * 0.08838834764831845f;   // 1/sqrt(128)
    }
    __syncthreads();

    // Row softmax (16 rows x 16 entries — serial per row, 16 active threads)
    if (tid < 16) {
        float m = -3.4e38f;
        #pragma unroll
        for (int j = 0; j < 16; j++) m = fmaxf(m, e_s[tid][j]);
        float s = 0.f;
        #pragma unroll
        for (int j = 0; j < 16; j++) {
            float ex = expf(e_s[tid][j] - m);
            e_s[tid][j] = ex;
            s += ex;
        }
        const float inv = 1.f / s;
        #pragma unroll
        for (int j = 0; j < 16; j++) e_s[tid][j] *= inv;
    }
    __syncthreads();

    // O = A @ Vr : thread owns column d for 8 rows
    {
        const int d = tid & 127;
        const int g = tid >> 7;                 // 0 or 1
        #pragma unroll
        for (int ii = 0; ii < 8; ii++) {
            const int i = g * 8 + ii;
            float acc = 0.f;
            #pragma unroll
            for (int s = 0; s < 16; s++)
                acc = fmaf(e_s[i][s], v_s[s][d], acc);
            O[base + (size_t)i * HDIM + d] = acc;
        }
    }
}

// ---------------------------------------------------------------------------
// kernel_launch: graph-capturable (kernel launches on default stream only;
// cudaGetSymbolAddress is a pure address lookup — no alloc, no sync)
// Input order (metadata): values, keys, queries, Wv, Wk, Wq, Wo, bo
// ---------------------------------------------------------------------------
extern "C" void kernel_launch(void* const* d_in, const int* in_sizes, int n_in,
                              void* d_out, int out_size)
{
    const float* values  = (const float*)d_in[0];
    const float* keys    = (const float*)d_in[1];
    const float* queries = (const float*)d_in[2];
    const float* Wv      = (const float*)d_in[3];
    const float* Wk      = (const float*)d_in[4];
    const float* Wq      = (const float*)d_in[5];
    const float* Wo      = (const float*)d_in[6];
    const float* bo      = (const float*)d_in[7];
    float* out = (float*)d_out;

    float *q, *k, *v, *attn;
    cudaGetSymbolAddress((void**)&q,    g_q);
    cudaGetSymbolAddress((void**)&k,    g_k);
    cudaGetSymbolAddress((void**)&v,    g_v);
    cudaGetSymbolAddress((void**)&attn, g_attn);

    dim3 grid(EMBED / BN, MROWS / BM);   // (16, 32)

    sgemm_nt<<<grid, 256>>>(queries, Wq, nullptr, q, MROWS, EMBED, EMBED);
    sgemm_nt<<<grid, 256>>>(keys,    Wk, nullptr, k, MROWS, EMBED, EMBED);
    sgemm_nt<<<grid, 256>>>(values,  Wv, nullptr, v, MROWS, EMBED, EMBED);

    attn_kernel<<<MROWS, 256>>>(q, k, v, attn);

    sgemm_nt<<<grid, 256>>>(attn, Wo, bo, out, MROWS, EMBED, EMBED);
}

// round 8
// speedup vs baseline: 2.6145x; 2.6145x over previous
#include <cuda_runtime.h>
#include <math.h>
#include <stdint.h>

// Problem constants
#define EMBED 2048
#define NB    2
#define LSEQ  2048
#define HEADS 16
#define HDIM  128
#define MROWS (NB * LSEQ)          // 4096 rows in flattened [N*L, E] view

// ---------------------------------------------------------------------------
// Scratch: __device__ globals (allocation inside kernel_launch is forbidden)
// ---------------------------------------------------------------------------
__device__ float g_q[(size_t)MROWS * EMBED];
__device__ float g_k[(size_t)MROWS * EMBED];
__device__ float g_v[(size_t)MROWS * EMBED];
__device__ float g_attn[(size_t)MROWS * EMBED];

// ---------------------------------------------------------------------------
// TF32 tensor-core GEMM (NT): C[m,n] = sum_k A[m,k]*B[n,k] (+ bias[n])
// A: [M,K] row-major, B: [N,K] row-major  (computes A @ B^T)
//
// 128x128 block tile, BK=16, 256 threads (8 warps in 2x4), warp tile 64x32.
// mma.sync.m16n8k8.tf32. SMEM tiles are stored PRE-PERMUTED into the mma
// fragment layout (tf32-converted at store time), so per-fragment loads are
// conflict-free vectorized LDS.128 (A) / LDS.64 (B).
//
// A-fragment perm: element (m_in_tile16, k_in_tile8):
//   g=m%8, hi=(m/8)&1, t=k%4, kh=(k/4)&1 -> lane=g*4+t, reg=hi+2*kh
//   flat idx within stage = (mt*2+kt)*128 + lane*4 + reg
// B-fragment perm: element (n_in_tile8, k_in_tile8):
//   g=n%8, t=k%4, kh=(k/4)&1 -> lane=g*4+t, reg=kh
//   flat idx within stage = (nt*2+kt)*64 + lane*2 + reg
// ---------------------------------------------------------------------------
constexpr int BM = 128;
constexpr int BN = 128;
constexpr int BK = 16;
constexpr int A_STAGE = (BM / 16) * (BK / 8) * 128;   // 2048 u32 = 8 KB
constexpr int B_STAGE = (BN / 8) * (BK / 8) * 64;     // 2048 u32 = 8 KB

__device__ __forceinline__ uint32_t f2tf32(float f) {
    uint32_t u;
    asm("cvt.rna.tf32.f32 %0, %1;" : "=r"(u) : "f"(f));
    return u;
}

__device__ __forceinline__ void mma_tf32(float c[4],
    uint32_t a0, uint32_t a1, uint32_t a2, uint32_t a3,
    uint32_t b0, uint32_t b1)
{
    asm volatile(
        "mma.sync.aligned.m16n8k8.row.col.f32.tf32.tf32.f32 "
        "{%0,%1,%2,%3}, {%4,%5,%6,%7}, {%8,%9}, {%0,%1,%2,%3};"
        : "+f"(c[0]), "+f"(c[1]), "+f"(c[2]), "+f"(c[3])
        : "r"(a0), "r"(a1), "r"(a2), "r"(a3), "r"(b0), "r"(b1));
}

// Scatter one float4 of A (row lr, k-offsets k0..k0+3 within the tile) into
// the permuted SMEM stage.
__device__ __forceinline__ void storeA(uint32_t* s, int lr, int k0, float4 v) {
    const int mt = lr >> 4;
    const int g  = lr & 7;
    const int hi = (lr >> 3) & 1;
    const int kt = k0 >> 3;
    const int kh = (k0 >> 2) & 1;
    uint32_t* p = s + (((mt << 1) + kt) << 7) + (g << 4) + hi + (kh << 1);
    p[0]  = f2tf32(v.x);
    p[4]  = f2tf32(v.y);
    p[8]  = f2tf32(v.z);
    p[12] = f2tf32(v.w);
}

__device__ __forceinline__ void storeB(uint32_t* s, int lr, int k0, float4 v) {
    const int nt = lr >> 3;
    const int g  = lr & 7;
    const int kt = k0 >> 3;
    const int kh = (k0 >> 2) & 1;
    uint32_t* p = s + (((nt << 1) + kt) << 6) + (g << 3) + kh;
    p[0] = f2tf32(v.x);
    p[2] = f2tf32(v.y);
    p[4] = f2tf32(v.z);
    p[6] = f2tf32(v.w);
}

__global__ __launch_bounds__(256) void gemm_tf32_nt(
    const float* __restrict__ A, const float* __restrict__ B,
    const float* __restrict__ bias, float* __restrict__ C,
    int M, int N, int K)
{
    __shared__ uint32_t As[2][A_STAGE];
    __shared__ uint32_t Bs[2][B_STAGE];

    const int tid    = threadIdx.x;
    const int lane   = tid & 31;
    const int wid    = tid >> 5;
    const int warp_m = wid >> 2;       // 0..1  (64-row slabs)
    const int warp_n = wid & 3;        // 0..3  (32-col slabs)
    const int bm     = blockIdx.y * BM;
    const int bn     = blockIdx.x * BN;

    // Global loaders: thread -> tile row lr (0..127), k offset lk (0 or 8)
    const int lr = tid >> 1;
    const int lk = (tid & 1) * 8;

    const float* aPtr = A + (size_t)(bm + lr) * K + lk;
    const float* bPtr = B + (size_t)(bn + lr) * K + lk;

    // Prologue: tile 0 -> registers -> permuted SMEM stage 0
    float4 pa0 = *(const float4*)(aPtr);
    float4 pa1 = *(const float4*)(aPtr + 4);
    float4 pb0 = *(const float4*)(bPtr);
    float4 pb1 = *(const float4*)(bPtr + 4);

    storeA(As[0], lr, lk,     pa0);
    storeA(As[0], lr, lk + 4, pa1);
    storeB(Bs[0], lr, lk,     pb0);
    storeB(Bs[0], lr, lk + 4, pb1);
    __syncthreads();

    float acc[4][4][4];
    #pragma unroll
    for (int i = 0; i < 4; i++)
        #pragma unroll
        for (int j = 0; j < 4; j++)
            #pragma unroll
            for (int r = 0; r < 4; r++) acc[i][j][r] = 0.f;

    const int ntiles = K / BK;
    for (int t = 0; t < ntiles; t++) {
        const int cur = t & 1;
        const int nxt = cur ^ 1;
        const bool has_next = (t + 1 < ntiles);

        // prefetch next K-tile into registers (overlaps with 64 HMMAs below)
        if (has_next) {
            const float* ap = aPtr + (size_t)(t + 1) * BK;
            const float* bp = bPtr + (size_t)(t + 1) * BK;
            pa0 = *(const float4*)(ap);
            pa1 = *(const float4*)(ap + 4);
            pb0 = *(const float4*)(bp);
            pb1 = *(const float4*)(bp + 4);
        }

        #pragma unroll
        for (int kt = 0; kt < 2; kt++) {
            uint4 af[4];
            uint2 bf[4];
            #pragma unroll
            for (int i = 0; i < 4; i++) {
                const int mt = warp_m * 4 + i;
                af[i] = *(const uint4*)&As[cur][(((mt << 1) + kt) << 7) + (lane << 2)];
            }
            #pragma unroll
            for (int j = 0; j < 4; j++) {
                const int nt = warp_n * 4 + j;
                bf[j] = *(const uint2*)&Bs[cur][(((nt << 1) + kt) << 6) + (lane << 1)];
            }
            #pragma unroll
            for (int i = 0; i < 4; i++)
                #pragma unroll
                for (int j = 0; j < 4; j++)
                    mma_tf32(acc[i][j], af[i].x, af[i].y, af[i].z, af[i].w,
                             bf[j].x, bf[j].y);
        }

        if (has_next) {
            storeA(As[nxt], lr, lk,     pa0);
            storeA(As[nxt], lr, lk + 4, pa1);
            storeB(Bs[nxt], lr, lk,     pb0);
            storeB(Bs[nxt], lr, lk + 4, pb1);
            __syncthreads();
        }
    }

    // Epilogue: C fragment -> global (+ optional bias), float2 stores
    #pragma unroll
    for (int j = 0; j < 4; j++) {
        const int col = bn + warp_n * 32 + j * 8 + (lane & 3) * 2;
        float b0 = 0.f, b1 = 0.f;
        if (bias) { b0 = bias[col]; b1 = bias[col + 1]; }
        #pragma unroll
        for (int i = 0; i < 4; i++) {
            const int row0 = bm + warp_m * 64 + i * 16 + (lane >> 2);
            float2 v01, v23;
            v01.x = acc[i][j][0] + b0; v01.y = acc[i][j][1] + b1;
            v23.x = acc[i][j][2] + b0; v23.y = acc[i][j][3] + b1;
            *(float2*)&C[(size_t)row0 * N + col]       = v01;
            *(float2*)&C[(size_t)(row0 + 8) * N + col] = v23;
        }
    }
}

// ---------------------------------------------------------------------------
// Per-position head-mixing attention (unchanged; 68us, 1-6% of total).
// The reference einsum's t,s index HEADS and h indexes sequence: for each
// (b,l): E = Qr@Kr^T/sqrt(128) (16x16), row softmax, O = A@Vr (16x128).
// ---------------------------------------------------------------------------
__global__ __launch_bounds__(256) void attn_kernel(
    const float* __restrict__ Q, const float* __restrict__ K,
    const float* __restrict__ V, float* __restrict__ O)
{
    __shared__ float q_s[16][132];
    __shared__ float k_s[16][132];
    __shared__ float v_s[16][132];
    __shared__ float e_s[16][17];

    const int row = blockIdx.x;                 // b*L + l
    const int tid = threadIdx.x;
    const size_t base = (size_t)row * EMBED;

    #pragma unroll
    for (int i = 0; i < 2; i++) {
        const int idx = tid + i * 256;
        const int h = idx >> 5;
        const int d = (idx & 31) * 4;
        const size_t g = base + (size_t)h * HDIM + d;
        *(float4*)&q_s[h][d] = *(const float4*)(Q + g);
        *(float4*)&k_s[h][d] = *(const float4*)(K + g);
        *(float4*)&v_s[h][d] = *(const float4*)(V + g);
    }
    __syncthreads();

    {
        const int ei = tid >> 4, ej = tid & 15;
        float e = 0.f;
        #pragma unroll
        for (int d = 0; d < HDIM; d++)
            e = fmaf(q_s[ei][d], k_s[ej][d], e);
        e_s[ei][ej] = e * 0.08838834764831845f;   // 1/sqrt(128)
    }
    __syncthreads();

    if (tid < 16) {
        float m = -3.4e38f;
        #pragma unroll
        for (int j = 0; j < 16; j++) m = fmaxf(m, e_s[tid][j]);
        float s = 0.f;
        #pragma unroll
        for (int j = 0; j < 16; j++) {
            float ex = expf(e_s[tid][j] - m);
            e_s[tid][j] = ex;
            s += ex;
        }
        const float inv = 1.f / s;
        #pragma unroll
        for (int j = 0; j < 16; j++) e_s[tid][j] *= inv;
    }
    __syncthreads();

    {
        const int d = tid & 127;
        const int g = tid >> 7;
        #pragma unroll
        for (int ii = 0; ii < 8; ii++) {
            const int i = g * 8 + ii;
            float acc = 0.f;
            #pragma unroll
            for (int s = 0; s < 16; s++)
                acc = fmaf(e_s[i][s], v_s[s][d], acc);
            O[base + (size_t)i * HDIM + d] = acc;
        }
    }
}

// ---------------------------------------------------------------------------
// kernel_launch: graph-capturable (kernel launches only; cudaGetSymbolAddress
// is a pure address lookup — no alloc, no sync)
// Input order (metadata): values, keys, queries, Wv, Wk, Wq, Wo, bo
// ---------------------------------------------------------------------------
extern "C" void kernel_launch(void* const* d_in, const int* in_sizes, int n_in,
                              void* d_out, int out_size)
{
    const float* values  = (const float*)d_in[0];
    const float* keys    = (const float*)d_in[1];
    const float* queries = (const float*)d_in[2];
    const float* Wv      = (const float*)d_in[3];
    const float* Wk      = (const float*)d_in[4];
    const float* Wq      = (const float*)d_in[5];
    const float* Wo      = (const float*)d_in[6];
    const float* bo      = (const float*)d_in[7];
    float* out = (float*)d_out;

    float *q, *k, *v, *attn;
    cudaGetSymbolAddress((void**)&q,    g_q);
    cudaGetSymbolAddress((void**)&k,    g_k);
    cudaGetSymbolAddress((void**)&v,    g_v);
    cudaGetSymbolAddress((void**)&attn, g_attn);

    dim3 grid(EMBED / BN, MROWS / BM);   // (16, 32)

    gemm_tf32_nt<<<grid, 256>>>(queries, Wq, nullptr, q, MROWS, EMBED, EMBED);
    gemm_tf32_nt<<<grid, 256>>>(keys,    Wk, nullptr, k, MROWS, EMBED, EMBED);
    gemm_tf32_nt<<<grid, 256>>>(values,  Wv, nullptr, v, MROWS, EMBED, EMBED);

    attn_kernel<<<MROWS, 256>>>(q, k, v, attn);

    gemm_tf32_nt<<<grid, 256>>>(attn, Wo, bo, out, MROWS, EMBED, EMBED);
}

// round 10
// speedup vs baseline: 5.6001x; 2.1419x over previous
#include <cuda_runtime.h>
#include <math.h>
#include <stdint.h>

// Problem constants
#define EMBED 2048
#define NB    2
#define LSEQ  2048
#define HEADS 16
#define HDIM  128
#define MROWS (NB * LSEQ)          // 4096 rows in flattened [N*L, E] view

// ---------------------------------------------------------------------------
// Scratch (__device__ globals; allocation in kernel_launch is forbidden)
// ---------------------------------------------------------------------------
__device__ float g_q[(size_t)MROWS * EMBED];
__device__ float g_k[(size_t)MROWS * EMBED];
__device__ float g_v[(size_t)MROWS * EMBED];
__device__ float g_attn[(size_t)MROWS * EMBED];
// tf32-pre-rounded operands (hardware truncation of pre-rounded == rna round)
__device__ float g_rq[(size_t)MROWS * EMBED];
__device__ float g_rk[(size_t)MROWS * EMBED];
__device__ float g_rv[(size_t)MROWS * EMBED];
__device__ float g_rWq[(size_t)EMBED * EMBED];
__device__ float g_rWk[(size_t)EMBED * EMBED];
__device__ float g_rWv[(size_t)EMBED * EMBED];
__device__ float g_rWo[(size_t)EMBED * EMBED];

// ---------------------------------------------------------------------------
// Helpers (sm_103 base-target safe: cp.async + mma.sync only, NO tcgen05)
// ---------------------------------------------------------------------------
__device__ __forceinline__ float round_tf32(float f) {
    uint32_t u;
    asm("cvt.rna.tf32.f32 %0, %1;" : "=r"(u) : "f"(f));
    return __uint_as_float(u);
}

__device__ __forceinline__ uint32_t smem_u32(const void* p) {
    uint32_t a;
    asm("{ .reg .u64 t; cvta.to.shared.u64 t, %1; cvt.u32.u64 %0, t; }"
        : "=r"(a) : "l"(p));
    return a;
}

__device__ __forceinline__ void cp16(uint32_t saddr, const void* gaddr) {
    asm volatile("cp.async.cg.shared.global [%0], [%1], 16;"
                 :: "r"(saddr), "l"(gaddr) : "memory");
}
#define CP_COMMIT() asm volatile("cp.async.commit_group;" ::: "memory")
#define CP_WAIT1()  asm volatile("cp.async.wait_group 1;" ::: "memory")

__device__ __forceinline__ uint32_t lds32(uint32_t a) {
    uint32_t v;
    asm("ld.shared.b32 %0, [%1];" : "=r"(v) : "r"(a));
    return v;
}

// SW128 swizzle on byte offsets (tile rows are 128 B)
__device__ __forceinline__ uint32_t swz(uint32_t x) { return x ^ ((x >> 3) & 0x70); }

__device__ __forceinline__ void mma_tf32(float c[4],
    uint32_t a0, uint32_t a1, uint32_t a2, uint32_t a3,
    uint32_t b0, uint32_t b1)
{
    asm volatile(
        "mma.sync.aligned.m16n8k8.row.col.f32.tf32.tf32.f32 "
        "{%0,%1,%2,%3}, {%4,%5,%6,%7}, {%8,%9}, {%0,%1,%2,%3};"
        : "+f"(c[0]), "+f"(c[1]), "+f"(c[2]), "+f"(c[3])
        : "r"(a0), "r"(a1), "r"(a2), "r"(a3), "r"(b0), "r"(b1));
}

// ---------------------------------------------------------------------------
// TF32 mma.sync GEMM (NT): C[m,n] = sum_k A[m,k]*B[n,k] (+ bias[n])
// A:[M,K] row-major, B:[N,K] row-major. Inputs must be tf32-pre-rounded.
//
// 128x128 block tile, BK=32, 256 threads (8 warps 2x4), warp tile 64x32.
// SW128 K-major tiles (128 rows x 128B = 16KB each), cp.async.cg feed,
// 3-stage pipeline (96KB dynamic smem), one __syncthreads per K-tile.
// Fragment loads are conflict-free scalar LDS.32 from the swizzled tile.
// ---------------------------------------------------------------------------
constexpr int BK      = 32;
constexpr int NSTAGE  = 3;
constexpr int STAGE_B = 32768;                 // 16KB A + 16KB B
#define GEMM_SMEM_BYTES (NSTAGE * STAGE_B)     // 98304

__global__ __launch_bounds__(256, 2) void gemm_tf32_nt(
    const float* __restrict__ A, const float* __restrict__ B,
    const float* __restrict__ bias, float* __restrict__ C,
    int M, int N, int K)
{
    extern __shared__ __align__(128) char smem[];
    const uint32_t sbase = smem_u32(smem);

    const int tid    = threadIdx.x;
    const int lane   = tid & 31;
    const int wid    = tid >> 5;
    const int warp_m = wid >> 2;              // 0..1 (64-row slabs)
    const int warp_n = wid & 3;               // 0..3 (32-col slabs)
    const int bm     = blockIdx.y * 128;
    const int bn     = blockIdx.x * 128;

    // Loader mapping: 1024 16B-chunks per 16KB tile; thread handles chunks
    // {tid, tid+256, tid+512, tid+768}: row = tid>>3 + 32*i, kq = tid&7.
    const int lrow0 = tid >> 3;
    const int lkq   = tid & 7;
    const float* aG0 = A + (size_t)(bm + lrow0) * K + lkq * 4;
    const float* bG0 = B + (size_t)(bn + lrow0) * K + lkq * 4;
    const uint32_t sOff0 = swz((uint32_t)(lrow0 * 128 + lkq * 16));
    const size_t gStep = (size_t)32 * K;      // +32 rows per chunk group

    auto issue = [&](int stage, int ktile) {
        const uint32_t sa = sbase + stage * STAGE_B;
        const uint32_t sb = sa + 16384u;
        const int ko = ktile * BK;
        #pragma unroll
        for (int i = 0; i < 4; i++) {
            const uint32_t so = sOff0 + i * 4096u;   // row%8 invariant under +32
            cp16(sa + so, aG0 + i * gStep + ko);
            cp16(sb + so, bG0 + i * gStep + ko);
        }
        CP_COMMIT();
    };

    issue(0, 0);
    issue(1, 1);

    float acc[4][4][4];
    #pragma unroll
    for (int i = 0; i < 4; i++)
        #pragma unroll
        for (int j = 0; j < 4; j++)
            #pragma unroll
            for (int r = 0; r < 4; r++) acc[i][j][r] = 0.f;

    const int g  = lane >> 2;                 // fragment group row 0..7
    const int tq = lane & 3;                  // fragment k-quad 0..3
    const int ntiles = K / BK;                // 64

    for (int t = 0; t < ntiles; t++) {
        CP_WAIT1();                            // oldest pending stage is ready
        __syncthreads();                       // all warps done with stage t-1

        if (t + 2 < ntiles) issue((t + 2) % NSTAGE, t + 2);

        const uint32_t sa = sbase + (t % NSTAGE) * STAGE_B;
        const uint32_t sb = sa + 16384u;

        #pragma unroll
        for (int kt = 0; kt < 4; kt++) {       // 4 x K=8 steps in BK=32
            const uint32_t kb0 = (uint32_t)((kt * 8 + tq) * 4);
            const uint32_t kb4 = kb0 + 16u;

            uint32_t af[4][4];
            #pragma unroll
            for (int i = 0; i < 4; i++) {
                const uint32_t r0 = (uint32_t)((warp_m * 64 + i * 16 + g) * 128);
                af[i][0] = lds32(sa + swz(r0 + kb0));
                af[i][1] = lds32(sa + swz(r0 + 1024u + kb0));   // +8 rows
                af[i][2] = lds32(sa + swz(r0 + kb4));
                af[i][3] = lds32(sa + swz(r0 + 1024u + kb4));
            }
            uint32_t bf[4][2];
            #pragma unroll
            for (int j = 0; j < 4; j++) {
                const uint32_t r0 = (uint32_t)((warp_n * 32 + j * 8 + g) * 128);
                bf[j][0] = lds32(sb + swz(r0 + kb0));
                bf[j][1] = lds32(sb + swz(r0 + kb4));
            }
            #pragma unroll
            for (int i = 0; i < 4; i++)
                #pragma unroll
                for (int j = 0; j < 4; j++)
                    mma_tf32(acc[i][j], af[i][0], af[i][1], af[i][2], af[i][3],
                             bf[j][0], bf[j][1]);
        }
    }

    // Epilogue: fragment -> global (+ optional bias), float2 stores
    #pragma unroll
    for (int j = 0; j < 4; j++) {
        const int col = bn + warp_n * 32 + j * 8 + tq * 2;
        float b0 = 0.f, b1 = 0.f;
        if (bias) { b0 = bias[col]; b1 = bias[col + 1]; }
        #pragma unroll
        for (int i = 0; i < 4; i++) {
            const int row0 = bm + warp_m * 64 + i * 16 + g;
            float2 v01, v23;
            v01.x = acc[i][j][0] + b0; v01.y = acc[i][j][1] + b1;
            v23.x = acc[i][j][2] + b0; v23.y = acc[i][j][3] + b1;
            *(float2*)&C[(size_t)row0 * N + col]       = v01;
            *(float2*)&C[(size_t)(row0 + 8) * N + col] = v23;
        }
    }
}

// ---------------------------------------------------------------------------
// Elementwise tf32 rounding pass (rna), float4 vectorized
// ---------------------------------------------------------------------------
__global__ __launch_bounds__(256) void round_tf32_kernel(
    const float4* __restrict__ src, float4* __restrict__ dst, int n4)
{
    const int i = blockIdx.x * 256 + threadIdx.x;
    if (i >= n4) return;
    float4 v = src[i];
    v.x = round_tf32(v.x); v.y = round_tf32(v.y);
    v.z = round_tf32(v.z); v.w = round_tf32(v.w);
    dst[i] = v;
}

// ---------------------------------------------------------------------------
// Per-position head-mixing attention (einsum t,s index HEADS; h = sequence):
// per (b,l): E = Qr@Kr^T/sqrt(128) (16x16), row softmax, O = A@Vr (16x128).
// Output pre-rounded to tf32 (feeds the final GEMM as operand A).
// ---------------------------------------------------------------------------
__global__ __launch_bounds__(256) void attn_kernel(
    const float* __restrict__ Q, const float* __restrict__ K,
    const float* __restrict__ V, float* __restrict__ O)
{
    __shared__ float q_s[16][132];
    __shared__ float k_s[16][132];
    __shared__ float v_s[16][132];
    __shared__ float e_s[16][17];

    const int row = blockIdx.x;
    const int tid = threadIdx.x;
    const size_t base = (size_t)row * EMBED;

    #pragma unroll
    for (int i = 0; i < 2; i++) {
        const int idx = tid + i * 256;
        const int h = idx >> 5;
        const int d = (idx & 31) * 4;
        const size_t gg = base + (size_t)h * HDIM + d;
        *(float4*)&q_s[h][d] = *(const float4*)(Q + gg);
        *(float4*)&k_s[h][d] = *(const float4*)(K + gg);
        *(float4*)&v_s[h][d] = *(const float4*)(V + gg);
    }
    __syncthreads();

    {
        const int ei = tid >> 4, ej = tid & 15;
        float e = 0.f;
        #pragma unroll
        for (int d = 0; d < HDIM; d++)
            e = fmaf(q_s[ei][d], k_s[ej][d], e);
        e_s[ei][ej] = e * 0.08838834764831845f;   // 1/sqrt(128)
    }
    __syncthreads();

    if (tid < 16) {
        float m = -3.4e38f;
        #pragma unroll
        for (int j = 0; j < 16; j++) m = fmaxf(m, e_s[tid][j]);
        float s = 0.f;
        #pragma unroll
        for (int j = 0; j < 16; j++) {
            float ex = expf(e_s[tid][j] - m);
            e_s[tid][j] = ex;
            s += ex;
        }
        const float inv = 1.f / s;
        #pragma unroll
        for (int j = 0; j < 16; j++) e_s[tid][j] *= inv;
    }
    __syncthreads();

    {
        const int d = tid & 127;
        const int gg = tid >> 7;
        #pragma unroll
        for (int ii = 0; ii < 8; ii++) {
            const int i = gg * 8 + ii;
            float acc = 0.f;
            #pragma unroll
            for (int s = 0; s < 16; s++)
                acc = fmaf(e_s[i][s], v_s[s][d], acc);
            O[base + (size_t)i * HDIM + d] = round_tf32(acc);
        }
    }
}

// ---------------------------------------------------------------------------
// kernel_launch (graph-capturable: kernel launches only)
// Input order (metadata): values, keys, queries, Wv, Wk, Wq, Wo, bo
// ---------------------------------------------------------------------------
extern "C" void kernel_launch(void* const* d_in, const int* in_sizes, int n_in,
                              void* d_out, int out_size)
{
    const float* values  = (const float*)d_in[0];
    const float* keys    = (const float*)d_in[1];
    const float* queries = (const float*)d_in[2];
    const float* Wv      = (const float*)d_in[3];
    const float* Wk      = (const float*)d_in[4];
    const float* Wq      = (const float*)d_in[5];
    const float* Wo      = (const float*)d_in[6];
    const float* bo      = (const float*)d_in[7];
    float* out = (float*)d_out;

    float *q, *k, *v, *attn, *rq, *rk, *rv, *rWq, *rWk, *rWv, *rWo;
    cudaGetSymbolAddress((void**)&q,    g_q);
    cudaGetSymbolAddress((void**)&k,    g_k);
    cudaGetSymbolAddress((void**)&v,    g_v);
    cudaGetSymbolAddress((void**)&attn, g_attn);
    cudaGetSymbolAddress((void**)&rq,   g_rq);
    cudaGetSymbolAddress((void**)&rk,   g_rk);
    cudaGetSymbolAddress((void**)&rv,   g_rv);
    cudaGetSymbolAddress((void**)&rWq,  g_rWq);
    cudaGetSymbolAddress((void**)&rWk,  g_rWk);
    cudaGetSymbolAddress((void**)&rWv,  g_rWv);
    cudaGetSymbolAddress((void**)&rWo,  g_rWo);

    cudaFuncSetAttribute(gemm_tf32_nt,
                         cudaFuncAttributeMaxDynamicSharedMemorySize,
                         GEMM_SMEM_BYTES);

    const int nAct4 = (MROWS * EMBED) / 4;
    const int nW4   = (EMBED * EMBED) / 4;

    round_tf32_kernel<<<nAct4 / 256, 256>>>((const float4*)queries, (float4*)rq, nAct4);
    round_tf32_kernel<<<nAct4 / 256, 256>>>((const float4*)keys,    (float4*)rk, nAct4);
    round_tf32_kernel<<<nAct4 / 256, 256>>>((const float4*)values,  (float4*)rv, nAct4);
    round_tf32_kernel<<<nW4 / 256, 256>>>((const float4*)Wq, (float4*)rWq, nW4);
    round_tf32_kernel<<<nW4 / 256, 256>>>((const float4*)Wk, (float4*)rWk, nW4);
    round_tf32_kernel<<<nW4 / 256, 256>>>((const float4*)Wv, (float4*)rWv, nW4);
    round_tf32_kernel<<<nW4 / 256, 256>>>((const float4*)Wo, (float4*)rWo, nW4);

    dim3 grid(EMBED / 128, MROWS / 128);   // (16, 32)

    gemm_tf32_nt<<<grid, 256, GEMM_SMEM_BYTES>>>(rq, rWq, nullptr, q, MROWS, EMBED, EMBED);
    gemm_tf32_nt<<<grid, 256, GEMM_SMEM_BYTES>>>(rk, rWk, nullptr, k, MROWS, EMBED, EMBED);
    gemm_tf32_nt<<<grid, 256, GEMM_SMEM_BYTES>>>(rv, rWv, nullptr, v, MROWS, EMBED, EMBED);

    attn_kernel<<<MROWS, 256>>>(q, k, v, attn);

    gemm_tf32_nt<<<grid, 256, GEMM_SMEM_BYTES>>>(attn, rWo, bo, out, MROWS, EMBED, EMBED);
}

// round 11
// speedup vs baseline: 6.0375x; 1.0781x over previous
#include <cuda_runtime.h>
#include <math.h>
#include <stdint.h>

// Problem constants
#define EMBED 2048
#define NB    2
#define LSEQ  2048
#define HEADS 16
#define HDIM  128
#define MROWS (NB * LSEQ)          // 4096 rows in flattened [N*L, E] view

// ---------------------------------------------------------------------------
// Scratch (__device__ globals; allocation in kernel_launch is forbidden)
// ---------------------------------------------------------------------------
__device__ float g_q[(size_t)MROWS * EMBED];
__device__ float g_k[(size_t)MROWS * EMBED];
__device__ float g_v[(size_t)MROWS * EMBED];
__device__ float g_attn[(size_t)MROWS * EMBED];
// tf32-pre-rounded operands (hardware truncation of pre-rounded == rna round)
__device__ float g_rq[(size_t)MROWS * EMBED];
__device__ float g_rk[(size_t)MROWS * EMBED];
__device__ float g_rv[(size_t)MROWS * EMBED];
__device__ float g_rWq[(size_t)EMBED * EMBED];
__device__ float g_rWk[(size_t)EMBED * EMBED];
__device__ float g_rWv[(size_t)EMBED * EMBED];
__device__ float g_rWo[(size_t)EMBED * EMBED];

// ---------------------------------------------------------------------------
// Helpers (sm_103 base-target safe: cp.async + mma.sync only, NO tcgen05)
// ---------------------------------------------------------------------------
__device__ __forceinline__ float round_tf32(float f) {
    uint32_t u;
    asm("cvt.rna.tf32.f32 %0, %1;" : "=r"(u) : "f"(f));
    return __uint_as_float(u);
}

__device__ __forceinline__ uint32_t smem_u32(const void* p) {
    uint32_t a;
    asm("{ .reg .u64 t; cvta.to.shared.u64 t, %1; cvt.u32.u64 %0, t; }"
        : "=r"(a) : "l"(p));
    return a;
}

__device__ __forceinline__ void cp16(uint32_t saddr, const void* gaddr) {
    asm volatile("cp.async.cg.shared.global [%0], [%1], 16;"
                 :: "r"(saddr), "l"(gaddr) : "memory");
}
#define CP_COMMIT() asm volatile("cp.async.commit_group;" ::: "memory")
#define CP_WAIT1()  asm volatile("cp.async.wait_group 1;" ::: "memory")

__device__ __forceinline__ uint32_t lds32(uint32_t a) {
    uint32_t v;
    asm("ld.shared.b32 %0, [%1];" : "=r"(v) : "r"(a));
    return v;
}

// SW128 swizzle on byte offsets (tile rows are 128 B)
__device__ __forceinline__ uint32_t swz(uint32_t x) { return x ^ ((x >> 3) & 0x70); }

__device__ __forceinline__ void mma_tf32(float c[4],
    uint32_t a0, uint32_t a1, uint32_t a2, uint32_t a3,
    uint32_t b0, uint32_t b1)
{
    asm volatile(
        "mma.sync.aligned.m16n8k8.row.col.f32.tf32.tf32.f32 "
        "{%0,%1,%2,%3}, {%4,%5,%6,%7}, {%8,%9}, {%0,%1,%2,%3};"
        : "+f"(c[0]), "+f"(c[1]), "+f"(c[2]), "+f"(c[3])
        : "r"(a0), "r"(a1), "r"(a2), "r"(a3), "r"(b0), "r"(b1));
}

// ---------------------------------------------------------------------------
// TF32 mma.sync GEMM (NT): C[m,n] = sum_k A[m,k]*B[n,k] (+ bias[n])
// A:[M,K] row-major, B:[N,K] row-major. Inputs must be tf32-pre-rounded.
//
// 128x128 block tile, BK=32, 128 threads = 4 warps (2x2), WARP TILE 64x64:
// per k8-step each warp does 32 LDS.32 for 32 HMMAs (MAC:LDS-byte ratio 2x
// the previous 64x32 warp tile). SW128 K-major tiles (16KB each), cp.async
// feed, 3-stage pipeline (96KB smem, 2 CTAs/SM), one barrier per K-tile.
// ---------------------------------------------------------------------------
constexpr int BK      = 32;
constexpr int NSTAGE  = 3;
constexpr int STAGE_B = 32768;                 // 16KB A + 16KB B
#define GEMM_SMEM_BYTES (NSTAGE * STAGE_B)     // 98304

__global__ __launch_bounds__(128, 2) void gemm_tf32_nt(
    const float* __restrict__ A, const float* __restrict__ B,
    const float* __restrict__ bias, float* __restrict__ C,
    int M, int N, int K)
{
    extern __shared__ __align__(128) char smem[];
    const uint32_t sbase = smem_u32(smem);

    const int tid    = threadIdx.x;
    const int lane   = tid & 31;
    const int wid    = tid >> 5;
    const int warp_m = wid >> 1;              // 0..1 (64-row slabs)
    const int warp_n = wid & 1;               // 0..1 (64-col slabs)
    const int bm     = blockIdx.y * 128;
    const int bn     = blockIdx.x * 128;

    // Loader mapping: 1024 16B-chunks per 16KB tile; thread handles chunks
    // {tid + 128*i, i=0..7}: row = tid>>3 + 16*i, kq = tid&7. 8 A + 8 B.
    const int lrow0 = tid >> 3;
    const int lkq   = tid & 7;
    const float* aG0 = A + (size_t)(bm + lrow0) * K + lkq * 4;
    const float* bG0 = B + (size_t)(bn + lrow0) * K + lkq * 4;
    const uint32_t sOff0 = swz((uint32_t)(lrow0 * 128 + lkq * 16));
    const size_t gStep = (size_t)16 * K;      // +16 rows per chunk group

    auto issue = [&](int stage, int ktile) {
        const uint32_t sa = sbase + stage * STAGE_B;
        const uint32_t sb = sa + 16384u;
        const int ko = ktile * BK;
        #pragma unroll
        for (int i = 0; i < 8; i++) {
            // row%8 invariant under +16 rows -> swizzle offset shifts by +2048
            const uint32_t so = sOff0 + i * 2048u;
            cp16(sa + so, aG0 + i * gStep + ko);
            cp16(sb + so, bG0 + i * gStep + ko);
        }
        CP_COMMIT();
    };

    issue(0, 0);
    issue(1, 1);

    float acc[4][8][4];
    #pragma unroll
    for (int i = 0; i < 4; i++)
        #pragma unroll
        for (int j = 0; j < 8; j++)
            #pragma unroll
            for (int r = 0; r < 4; r++) acc[i][j][r] = 0.f;

    const int g  = lane >> 2;                 // fragment group row 0..7
    const int tq = lane & 3;                  // fragment k-quad 0..3
    const int ntiles = K / BK;                // 64

    for (int t = 0; t < ntiles; t++) {
        CP_WAIT1();                            // oldest pending stage ready
        __syncthreads();                       // all warps done with stage t-1

        if (t + 2 < ntiles) issue((t + 2) % NSTAGE, t + 2);

        const uint32_t sa = sbase + (t % NSTAGE) * STAGE_B;
        const uint32_t sb = sa + 16384u;

        #pragma unroll
        for (int kt = 0; kt < 4; kt++) {       // 4 x K=8 steps in BK=32
            const uint32_t kb0 = (uint32_t)((kt * 8 + tq) * 4);
            const uint32_t kb4 = kb0 + 16u;

            uint32_t af[4][4];
            #pragma unroll
            for (int i = 0; i < 4; i++) {
                const uint32_t r0 = (uint32_t)((warp_m * 64 + i * 16 + g) * 128);
                af[i][0] = lds32(sa + swz(r0 + kb0));
                af[i][1] = lds32(sa + swz(r0 + 1024u + kb0));   // +8 rows
                af[i][2] = lds32(sa + swz(r0 + kb4));
                af[i][3] = lds32(sa + swz(r0 + 1024u + kb4));
            }
            uint32_t bf[8][2];
            #pragma unroll
            for (int j = 0; j < 8; j++) {
                const uint32_t r0 = (uint32_t)((warp_n * 64 + j * 8 + g) * 128);
                bf[j][0] = lds32(sb + swz(r0 + kb0));
                bf[j][1] = lds32(sb + swz(r0 + kb4));
            }
            #pragma unroll
            for (int i = 0; i < 4; i++)
                #pragma unroll
                for (int j = 0; j < 8; j++)
                    mma_tf32(acc[i][j], af[i][0], af[i][1], af[i][2], af[i][3],
                             bf[j][0], bf[j][1]);
        }
    }

    // Epilogue: fragment -> global (+ optional bias), float2 stores
    #pragma unroll
    for (int j = 0; j < 8; j++) {
        const int col = bn + warp_n * 64 + j * 8 + tq * 2;
        float b0 = 0.f, b1 = 0.f;
        if (bias) { b0 = bias[col]; b1 = bias[col + 1]; }
        #pragma unroll
        for (int i = 0; i < 4; i++) {
            const int row0 = bm + warp_m * 64 + i * 16 + g;
            float2 v01, v23;
            v01.x = acc[i][j][0] + b0; v01.y = acc[i][j][1] + b1;
            v23.x = acc[i][j][2] + b0; v23.y = acc[i][j][3] + b1;
            *(float2*)&C[(size_t)row0 * N + col]       = v01;
            *(float2*)&C[(size_t)(row0 + 8) * N + col] = v23;
        }
    }
}

// ---------------------------------------------------------------------------
// Batched elementwise tf32 rounding (rna): blockIdx.z picks the tensor.
// ---------------------------------------------------------------------------
__global__ __launch_bounds__(256) void round3_kernel(
    const float4* __restrict__ s0, float4* __restrict__ d0,
    const float4* __restrict__ s1, float4* __restrict__ d1,
    const float4* __restrict__ s2, float4* __restrict__ d2, int n4)
{
    const int i = blockIdx.x * 256 + threadIdx.x;
    if (i >= n4) return;
    const float4* s = (blockIdx.z == 0) ? s0 : (blockIdx.z == 1) ? s1 : s2;
    float4*       d = (blockIdx.z == 0) ? d0 : (blockIdx.z == 1) ? d1 : d2;
    float4 v = s[i];
    v.x = round_tf32(v.x); v.y = round_tf32(v.y);
    v.z = round_tf32(v.z); v.w = round_tf32(v.w);
    d[i] = v;
}

__global__ __launch_bounds__(256) void round4_kernel(
    const float4* __restrict__ s0, float4* __restrict__ d0,
    const float4* __restrict__ s1, float4* __restrict__ d1,
    const float4* __restrict__ s2, float4* __restrict__ d2,
    const float4* __restrict__ s3, float4* __restrict__ d3, int n4)
{
    const int i = blockIdx.x * 256 + threadIdx.x;
    if (i >= n4) return;
    const float4* s; float4* d;
    switch (blockIdx.z) {
        case 0:  s = s0; d = d0; break;
        case 1:  s = s1; d = d1; break;
        case 2:  s = s2; d = d2; break;
        default: s = s3; d = d3; break;
    }
    float4 v = s[i];
    v.x = round_tf32(v.x); v.y = round_tf32(v.y);
    v.z = round_tf32(v.z); v.w = round_tf32(v.w);
    d[i] = v;
}

// ---------------------------------------------------------------------------
// Per-position head-mixing attention (einsum t,s index HEADS; h = sequence):
// per (b,l): E = Qr@Kr^T/sqrt(128) (16x16), row softmax, O = A@Vr (16x128).
// Output pre-rounded to tf32 (feeds the final GEMM as operand A).
// ---------------------------------------------------------------------------
__global__ __launch_bounds__(256) void attn_kernel(
    const float* __restrict__ Q, const float* __restrict__ K,
    const float* __restrict__ V, float* __restrict__ O)
{
    __shared__ float q_s[16][132];
    __shared__ float k_s[16][132];
    __shared__ float v_s[16][132];
    __shared__ float e_s[16][17];

    const int row = blockIdx.x;
    const int tid = threadIdx.x;
    const size_t base = (size_t)row * EMBED;

    #pragma unroll
    for (int i = 0; i < 2; i++) {
        const int idx = tid + i * 256;
        const int h = idx >> 5;
        const int d = (idx & 31) * 4;
        const size_t gg = base + (size_t)h * HDIM + d;
        *(float4*)&q_s[h][d] = *(const float4*)(Q + gg);
        *(float4*)&k_s[h][d] = *(const float4*)(K + gg);
        *(float4*)&v_s[h][d] = *(const float4*)(V + gg);
    }
    __syncthreads();

    {
        const int ei = tid >> 4, ej = tid & 15;
        float e = 0.f;
        #pragma unroll
        for (int d = 0; d < HDIM; d++)
            e = fmaf(q_s[ei][d], k_s[ej][d], e);
        e_s[ei][ej] = e * 0.08838834764831845f;   // 1/sqrt(128)
    }
    __syncthreads();

    if (tid < 16) {
        float m = -3.4e38f;
        #pragma unroll
        for (int j = 0; j < 16; j++) m = fmaxf(m, e_s[tid][j]);
        float s = 0.f;
        #pragma unroll
        for (int j = 0; j < 16; j++) {
            float ex = expf(e_s[tid][j] - m);
            e_s[tid][j] = ex;
            s += ex;
        }
        const float inv = 1.f / s;
        #pragma unroll
        for (int j = 0; j < 16; j++) e_s[tid][j] *= inv;
    }
    __syncthreads();

    {
        const int d = tid & 127;
        const int gg = tid >> 7;
        #pragma unroll
        for (int ii = 0; ii < 8; ii++) {
            const int i = gg * 8 + ii;
            float acc = 0.f;
            #pragma unroll
            for (int s = 0; s < 16; s++)
                acc = fmaf(e_s[i][s], v_s[s][d], acc);
            O[base + (size_t)i * HDIM + d] = round_tf32(acc);
        }
    }
}

// ---------------------------------------------------------------------------
// kernel_launch (graph-capturable: kernel launches only)
// Input order (metadata): values, keys, queries, Wv, Wk, Wq, Wo, bo
// ---------------------------------------------------------------------------
extern "C" void kernel_launch(void* const* d_in, const int* in_sizes, int n_in,
                              void* d_out, int out_size)
{
    const float* values  = (const float*)d_in[0];
    const float* keys    = (const float*)d_in[1];
    const float* queries = (const float*)d_in[2];
    const float* Wv      = (const float*)d_in[3];
    const float* Wk      = (const float*)d_in[4];
    const float* Wq      = (const float*)d_in[5];
    const float* Wo      = (const float*)d_in[6];
    const float* bo      = (const float*)d_in[7];
    float* out = (float*)d_out;

    float *q, *k, *v, *attn, *rq, *rk, *rv, *rWq, *rWk, *rWv, *rWo;
    cudaGetSymbolAddress((void**)&q,    g_q);
    cudaGetSymbolAddress((void**)&k,    g_k);
    cudaGetSymbolAddress((void**)&v,    g_v);
    cudaGetSymbolAddress((void**)&attn, g_attn);
    cudaGetSymbolAddress((void**)&rq,   g_rq);
    cudaGetSymbolAddress((void**)&rk,   g_rk);
    cudaGetSymbolAddress((void**)&rv,   g_rv);
    cudaGetSymbolAddress((void**)&rWq,  g_rWq);
    cudaGetSymbolAddress((void**)&rWk,  g_rWk);
    cudaGetSymbolAddress((void**)&rWv,  g_rWv);
    cudaGetSymbolAddress((void**)&rWo,  g_rWo);

    cudaFuncSetAttribute(gemm_tf32_nt,
                         cudaFuncAttributeMaxDynamicSharedMemorySize,
                         GEMM_SMEM_BYTES);

    const int nAct4 = (MROWS * EMBED) / 4;
    const int nW4   = (EMBED * EMBED) / 4;

    {
        dim3 ga(nAct4 / 256, 1, 3);
        round3_kernel<<<ga, 256>>>(
            (const float4*)queries, (float4*)rq,
            (const float4*)keys,    (float4*)rk,
            (const float4*)values,  (float4*)rv, nAct4);
        dim3 gw(nW4 / 256, 1, 4);
        round4_kernel<<<gw, 256>>>(
            (const float4*)Wq, (float4*)rWq,
            (const float4*)Wk, (float4*)rWk,
            (const float4*)Wv, (float4*)rWv,
            (const float4*)Wo, (float4*)rWo, nW4);
    }

    dim3 grid(EMBED / 128, MROWS / 128);   // (16, 32) = 512 CTAs, 2/SM

    gemm_tf32_nt<<<grid, 128, GEMM_SMEM_BYTES>>>(rq, rWq, nullptr, q, MROWS, EMBED, EMBED);
    gemm_tf32_nt<<<grid, 128, GEMM_SMEM_BYTES>>>(rk, rWk, nullptr, k, MROWS, EMBED, EMBED);
    gemm_tf32_nt<<<grid, 128, GEMM_SMEM_BYTES>>>(rv, rWv, nullptr, v, MROWS, EMBED, EMBED);

    attn_kernel<<<MROWS, 256>>>(q, k, v, attn);

    gemm_tf32_nt<<<grid, 128, GEMM_SMEM_BYTES>>>(attn, rWo, bo, out, MROWS, EMBED, EMBED);
}

// round 13
// speedup vs baseline: 6.8492x; 1.1344x over previous
#include <cuda_runtime.h>
#include <math.h>
#include <stdint.h>

// Problem constants
#define EMBED 2048
#define NB    2
#define LSEQ  2048
#define HEADS 16
#define HDIM  128
#define MROWS (NB * LSEQ)          // 4096 rows in flattened [N*L, E] view
#define KT64  (EMBED / 32)         // 64 K-tiles per GEMM

// ---------------------------------------------------------------------------
// Scratch (__device__ globals; allocation in kernel_launch is forbidden)
// ---------------------------------------------------------------------------
__device__ float g_q[(size_t)MROWS * EMBED];      // GEMM outputs, row-major
__device__ float g_k[(size_t)MROWS * EMBED];
__device__ float g_v[(size_t)MROWS * EMBED];
__device__ float g_attn[(size_t)MROWS * EMBED];   // attn output, row-major
// Fragment-packed + tf32-pre-rounded GEMM operands
__device__ float g_rq[(size_t)MROWS * EMBED];     // A-role pack
__device__ float g_rk[(size_t)MROWS * EMBED];
__device__ float g_rv[(size_t)MROWS * EMBED];
__device__ float g_attnp[(size_t)MROWS * EMBED];  // A-role pack of g_attn
__device__ float g_rWq[(size_t)EMBED * EMBED];    // B-role pack
__device__ float g_rWk[(size_t)EMBED * EMBED];
__device__ float g_rWv[(size_t)EMBED * EMBED];
__device__ float g_rWo[(size_t)EMBED * EMBED];

// ---------------------------------------------------------------------------
// Helpers (sm_103 base-target safe: cp.async + mma.sync, NO tcgen05)
// ---------------------------------------------------------------------------
__device__ __forceinline__ float round_tf32(float f) {
    uint32_t u;
    asm("cvt.rna.tf32.f32 %0, %1;" : "=r"(u) : "f"(f));
    return __uint_as_float(u);
}

__device__ __forceinline__ uint32_t smem_u32(const void* p) {
    uint32_t a;
    asm("{ .reg .u64 t; cvta.to.shared.u64 t, %1; cvt.u32.u64 %0, t; }"
        : "=r"(a) : "l"(p));
    return a;
}

__device__ __forceinline__ void cp16(uint32_t saddr, const void* gaddr) {
    asm volatile("cp.async.cg.shared.global [%0], [%1], 16;"
                 :: "r"(saddr), "l"(gaddr) : "memory");
}
#define CP_COMMIT() asm volatile("cp.async.commit_group;" ::: "memory")
#define CP_WAIT1()  asm volatile("cp.async.wait_group 1;" ::: "memory")

__device__ __forceinline__ void mma_tf32(float c[4],
    uint32_t a0, uint32_t a1, uint32_t a2, uint32_t a3,
    uint32_t b0, uint32_t b1)
{
    asm volatile(
        "mma.sync.aligned.m16n8k8.row.col.f32.tf32.tf32.f32 "
        "{%0,%1,%2,%3}, {%4,%5,%6,%7}, {%8,%9}, {%0,%1,%2,%3};"
        : "+f"(c[0]), "+f"(c[1]), "+f"(c[2]), "+f"(c[3])
        : "r"(a0), "r"(a1), "r"(a2), "r"(a3), "r"(b0), "r"(b1));
}

// ---------------------------------------------------------------------------
// Fragment-pack layouts (K is always EMBED=2048 here):
//  A-role (row-major src [R,2048]):
//    tile(rm,tk) = 16KB blob at (rm*64+tk)*4096 floats; within:
//    float4[(mt*4+kt)*32 + lane] = {S[m0][k0],S[m0+8][k0],S[m0][k0+4],S[m0+8][k0+4]}
//    m0 = rm*128+mt*16+(lane>>2), k0 = tk*32+kt*8+(lane&3)
//  B-role (row-major src [N,2048]):
//    tile(rn,tk) same blob size; within:
//    float2[(nt*4+kt)*32 + lane] = {S[n0][k0], S[n0][k0+4]}
//    n0 = rn*128+nt*8+(lane>>2), k0 = tk*32+kt*8+(lane&3)
// Both packs are tf32-rounded at write time (rna), so HW truncation is exact.
// ---------------------------------------------------------------------------

__global__ __launch_bounds__(256) void packA_round(
    const float4* __restrict__ s0, float4* __restrict__ d0,
    const float4* __restrict__ s1, float4* __restrict__ d1,
    const float4* __restrict__ s2, float4* __restrict__ d2, int total4)
{
    const int i = blockIdx.x * 256 + threadIdx.x;
    if (i >= total4) return;
    const float* s = (const float*)((blockIdx.z == 0) ? s0 : (blockIdx.z == 1) ? s1 : s2);
    float4*      d = (blockIdx.z == 0) ? d0 : (blockIdx.z == 1) ? d1 : d2;

    const int tile = i >> 10;            // 1024 float4 per 16KB tile
    const int w    = i & 1023;
    const int sub  = w >> 5;             // mt*4+kt
    const int lane = w & 31;
    const int mt = sub >> 2, kt = sub & 3;
    const int g  = lane >> 2, tq = lane & 3;
    const int rm = tile >> 6, tk = tile & 63;   // K/32 = 64
    const int m0 = rm * 128 + mt * 16 + g;
    const int k0 = tk * 32 + kt * 8 + tq;

    const float* p = s + (size_t)m0 * EMBED + k0;
    float4 o;
    o.x = round_tf32(p[0]);
    o.y = round_tf32(p[(size_t)8 * EMBED]);
    o.z = round_tf32(p[4]);
    o.w = round_tf32(p[(size_t)8 * EMBED + 4]);
    d[i] = o;
}

__global__ __launch_bounds__(256) void packB_round(
    const float* __restrict__ s0, float2* __restrict__ d0,
    const float* __restrict__ s1, float2* __restrict__ d1,
    const float* __restrict__ s2, float2* __restrict__ d2,
    const float* __restrict__ s3, float2* __restrict__ d3, int total2)
{
    const int i = blockIdx.x * 256 + threadIdx.x;
    if (i >= total2) return;
    const float* s; float2* d;
    switch (blockIdx.z) {
        case 0:  s = s0; d = d0; break;
        case 1:  s = s1; d = d1; break;
        case 2:  s = s2; d = d2; break;
        default: s = s3; d = d3; break;
    }
    const int tile = i >> 11;            // 2048 float2 per 16KB tile
    const int w    = i & 2047;
    const int sub  = w >> 5;             // nt*4+kt
    const int lane = w & 31;
    const int nt = sub >> 2, kt = sub & 3;
    const int g  = lane >> 2, tq = lane & 3;
    const int rn = tile >> 6, tk = tile & 63;
    const int n0 = rn * 128 + nt * 8 + g;
    const int k0 = tk * 32 + kt * 8 + tq;

    const float* p = s + (size_t)n0 * EMBED + k0;
    float2 o;
    o.x = round_tf32(p[0]);
    o.y = round_tf32(p[4]);
    d[i] = o;
}

// ---------------------------------------------------------------------------
// TF32 mma.sync GEMM (NT) on FRAGMENT-PACKED operands.
// C[m,n] = sum_k A[m,k]*B[n,k] (+ bias[n]); C row-major [M,N].
// 128x128 block tile, BK=32, 128 threads = 4 warps (2x2), warp tile 64x64.
// cp.async copies linear 16KB tile blobs; fragment loads are 4x LDS.128 (A)
// + 8x LDS.64 (B) per k8-step, conflict-free. 3-stage pipeline, 96KB smem.
// ---------------------------------------------------------------------------
constexpr int NSTAGE  = 3;
constexpr int STAGE_B = 32768;                 // 16KB A + 16KB B
#define GEMM_SMEM_BYTES (NSTAGE * STAGE_B)     // 98304

__global__ __launch_bounds__(128, 2) void gemm_tf32_nt(
    const float* __restrict__ Ap, const float* __restrict__ Bp,
    const float* __restrict__ bias, float* __restrict__ C,
    int M, int N, int K)
{
    extern __shared__ __align__(128) char smem[];
    const uint32_t sbase = smem_u32(smem);

    const int tid    = threadIdx.x;
    const int lane   = tid & 31;
    const int wid    = tid >> 5;
    const int warp_m = wid >> 1;              // 0..1 (64-row slabs)
    const int warp_n = wid & 1;               // 0..1 (64-col slabs)

    const float* aBase = Ap + (size_t)blockIdx.y * KT64 * 4096;
    const float* bBase = Bp + (size_t)blockIdx.x * KT64 * 4096;

    auto issue = [&](int stage, int ktile) {
        const uint32_t sa = sbase + stage * STAGE_B;
        const uint32_t sb = sa + 16384u;
        const float* aT = aBase + (size_t)ktile * 4096;
        const float* bT = bBase + (size_t)ktile * 4096;
        #pragma unroll
        for (int i = 0; i < 8; i++) {
            const int c = tid + 128 * i;      // 16B chunk id 0..1023
            cp16(sa + c * 16, aT + c * 4);
            cp16(sb + c * 16, bT + c * 4);
        }
        CP_COMMIT();
    };

    issue(0, 0);
    issue(1, 1);

    float acc[4][8][4];
    #pragma unroll
    for (int i = 0; i < 4; i++)
        #pragma unroll
        for (int j = 0; j < 8; j++)
            #pragma unroll
            for (int r = 0; r < 4; r++) acc[i][j][r] = 0.f;

    for (int t = 0; t < KT64; t++) {
        CP_WAIT1();
        __syncthreads();

        if (t + 2 < KT64) issue((t + 2) % NSTAGE, t + 2);

        const char* sa = smem + (t % NSTAGE) * STAGE_B;
        const char* sb = sa + 16384;

        #pragma unroll
        for (int kt = 0; kt < 4; kt++) {
            uint4 af[4];
            #pragma unroll
            for (int i = 0; i < 4; i++) {
                const int mt = warp_m * 4 + i;
                af[i] = *(const uint4*)(sa + ((mt * 4 + kt) * 32 + lane) * 16);
            }
            uint2 bf[8];
            #pragma unroll
            for (int j = 0; j < 8; j++) {
                const int nt = warp_n * 8 + j;
                bf[j] = *(const uint2*)(sb + ((nt * 4 + kt) * 32 + lane) * 8);
            }
            #pragma unroll
            for (int i = 0; i < 4; i++)
                #pragma unroll
                for (int j = 0; j < 8; j++)
                    mma_tf32(acc[i][j], af[i].x, af[i].y, af[i].z, af[i].w,
                             bf[j].x, bf[j].y);
        }
    }

    // Epilogue: fragment -> global (+ optional bias), float2 stores
    const int g  = lane >> 2;
    const int tq = lane & 3;
    const int bm = blockIdx.y * 128;
    const int bn = blockIdx.x * 128;
    #pragma unroll
    for (int j = 0; j < 8; j++) {
        const int col = bn + warp_n * 64 + j * 8 + tq * 2;
        float b0 = 0.f, b1 = 0.f;
        if (bias) { b0 = bias[col]; b1 = bias[col + 1]; }
        #pragma unroll
        for (int i = 0; i < 4; i++) {
            const int row0 = bm + warp_m * 64 + i * 16 + g;
            float2 v01, v23;
            v01.x = acc[i][j][0] + b0; v01.y = acc[i][j][1] + b1;
            v23.x = acc[i][j][2] + b0; v23.y = acc[i][j][3] + b1;
            *(float2*)&C[(size_t)row0 * N + col]       = v01;
            *(float2*)&C[(size_t)(row0 + 8) * N + col] = v23;
        }
    }
}

// ---------------------------------------------------------------------------
// Per-position head-mixing attention (einsum t,s index HEADS; h = sequence):
// per (b,l): E = Qr@Kr^T/sqrt(128) (16x16), row softmax, O = A@Vr (16x128).
// Output row-major + tf32-rounded (a packA pass re-packs it for the O-GEMM;
// rounding here keeps that pass's reads/writes idempotent).
// ---------------------------------------------------------------------------
__global__ __launch_bounds__(256) void attn_kernel(
    const float* __restrict__ Q, const float* __restrict__ K,
    const float* __restrict__ V, float* __restrict__ O)
{
    __shared__ float q_s[16][132];
    __shared__ float k_s[16][132];
    __shared__ float v_s[16][132];
    __shared__ float e_s[16][17];

    const int row = blockIdx.x;
    const int tid = threadIdx.x;
    const size_t base = (size_t)row * EMBED;

    #pragma unroll
    for (int i = 0; i < 2; i++) {
        const int idx = tid + i * 256;
        const int h = idx >> 5;
        const int d = (idx & 31) * 4;
        const size_t gg = base + (size_t)h * HDIM + d;
        *(float4*)&q_s[h][d] = *(const float4*)(Q + gg);
        *(float4*)&k_s[h][d] = *(const float4*)(K + gg);
        *(float4*)&v_s[h][d] = *(const float4*)(V + gg);
    }
    __syncthreads();

    {
        const int ei = tid >> 4, ej = tid & 15;
        float e = 0.f;
        #pragma unroll
        for (int d = 0; d < HDIM; d++)
            e = fmaf(q_s[ei][d], k_s[ej][d], e);
        e_s[ei][ej] = e * 0.08838834764831845f;   // 1/sqrt(128)
    }
    __syncthreads();

    if (tid < 16) {
        float m = -3.4e38f;
        #pragma unroll
        for (int j = 0; j < 16; j++) m = fmaxf(m, e_s[tid][j]);
        float s = 0.f;
        #pragma unroll
        for (int j = 0; j < 16; j++) {
            float ex = expf(e_s[tid][j] - m);
            e_s[tid][j] = ex;
            s += ex;
        }
        const float inv = 1.f / s;
        #pragma unroll
        for (int j = 0; j < 16; j++) e_s[tid][j] *= inv;
    }
    __syncthreads();

    {
        const int d = tid & 127;
        const int gg = tid >> 7;
        #pragma unroll
        for (int ii = 0; ii < 8; ii++) {
            const int i = gg * 8 + ii;
            float acc = 0.f;
            #pragma unroll
            for (int s = 0; s < 16; s++)
                acc = fmaf(e_s[i][s], v_s[s][d], acc);
            O[base + (size_t)i * HDIM + d] = round_tf32(acc);
        }
    }
}

// ---------------------------------------------------------------------------
// kernel_launch (graph-capturable: kernel launches only)
// Input order (metadata): values, keys, queries, Wv, Wk, Wq, Wo, bo
// ---------------------------------------------------------------------------
extern "C" void kernel_launch(void* const* d_in, const int* in_sizes, int n_in,
                              void* d_out, int out_size)
{
    const float* values  = (const float*)d_in[0];
    const float* keys    = (const float*)d_in[1];
    const float* queries = (const float*)d_in[2];
    const float* Wv      = (const float*)d_in[3];
    const float* Wk      = (const float*)d_in[4];
    const float* Wq      = (const float*)d_in[5];
    const float* Wo      = (const float*)d_in[6];
    const float* bo      = (const float*)d_in[7];
    float* out = (float*)d_out;

    float *q, *k, *v, *attn, *attnp, *rq, *rk, *rv, *rWq, *rWk, *rWv, *rWo;
    cudaGetSymbolAddress((void**)&q,     g_q);
    cudaGetSymbolAddress((void**)&k,     g_k);
    cudaGetSymbolAddress((void**)&v,     g_v);
    cudaGetSymbolAddress((void**)&attn,  g_attn);
    cudaGetSymbolAddress((void**)&attnp, g_attnp);
    cudaGetSymbolAddress((void**)&rq,    g_rq);
    cudaGetSymbolAddress((void**)&rk,    g_rk);
    cudaGetSymbolAddress((void**)&rv,    g_rv);
    cudaGetSymbolAddress((void**)&rWq,   g_rWq);
    cudaGetSymbolAddress((void**)&rWk,   g_rWk);
    cudaGetSymbolAddress((void**)&rWv,   g_rWv);
    cudaGetSymbolAddress((void**)&rWo,   g_rWo);

    cudaFuncSetAttribute(gemm_tf32_nt,
                         cudaFuncAttributeMaxDynamicSharedMemorySize,
                         GEMM_SMEM_BYTES);

    const int nAct4 = (MROWS * EMBED) / 4;    // 2,097,152 float4
    const int nW2   = (EMBED * EMBED) / 2;    // 2,097,152 float2

    // Pack+round activations (A-role) and weights (B-role)
    {
        dim3 ga(nAct4 / 256, 1, 3);
        packA_round<<<ga, 256>>>(
            (const float4*)queries, (float4*)rq,
            (const float4*)keys,    (float4*)rk,
            (const float4*)values,  (float4*)rv, nAct4);
        dim3 gw(nW2 / 256, 1, 4);
        packB_round<<<gw, 256>>>(
            Wq, (float2*)rWq, Wk, (float2*)rWk,
            Wv, (float2*)rWv, Wo, (float2*)rWo, nW2);
    }

    dim3 grid(EMBED / 128, MROWS / 128);   // (16, 32) = 512 CTAs, 2/SM

    gemm_tf32_nt<<<grid, 128, GEMM_SMEM_BYTES>>>(rq, rWq, nullptr, q, MROWS, EMBED, EMBED);
    gemm_tf32_nt<<<grid, 128, GEMM_SMEM_BYTES>>>(rk, rWk, nullptr, k, MROWS, EMBED, EMBED);
    gemm_tf32_nt<<<grid, 128, GEMM_SMEM_BYTES>>>(rv, rWv, nullptr, v, MROWS, EMBED, EMBED);

    attn_kernel<<<MROWS, 256>>>(q, k, v, attn);

    // Re-pack attn output as A-role operand for the output GEMM
    {
        dim3 gp(nAct4 / 256, 1, 1);
        packA_round<<<gp, 256>>>(
            (const float4*)attn, (float4*)attnp,
            (const float4*)attn, (float4*)attnp,
            (const float4*)attn, (float4*)attnp, nAct4);
    }

    gemm_tf32_nt<<<grid, 128, GEMM_SMEM_BYTES>>>(attnp, rWo, bo, out, MROWS, EMBED, EMBED);
}

// round 14
// speedup vs baseline: 7.6914x; 1.1230x over previous
#include <cuda_runtime.h>
#include <math.h>
#include <stdint.h>

// Problem constants
#define EMBED 2048
#define NB    2
#define LSEQ  2048
#define HEADS 16
#define HDIM  128
#define MROWS (NB * LSEQ)          // 4096 rows in flattened [N*L, E] view
#define KT64  (EMBED / 32)         // 64 K-tiles per GEMM

// ---------------------------------------------------------------------------
// Scratch (__device__ globals; allocation in kernel_launch is forbidden)
// ---------------------------------------------------------------------------
__device__ float g_q[(size_t)MROWS * EMBED];      // GEMM outputs, row-major
__device__ float g_k[(size_t)MROWS * EMBED];
__device__ float g_v[(size_t)MROWS * EMBED];
__device__ float g_attn[(size_t)MROWS * EMBED];   // attn output, row-major
// Fragment-packed + tf32-pre-rounded GEMM operands
__device__ float g_rq[(size_t)MROWS * EMBED];     // A-role pack
__device__ float g_rk[(size_t)MROWS * EMBED];
__device__ float g_rv[(size_t)MROWS * EMBED];
__device__ float g_attnp[(size_t)MROWS * EMBED];  // A-role pack of g_attn
__device__ float g_rWq[(size_t)EMBED * EMBED];    // B-role pack
__device__ float g_rWk[(size_t)EMBED * EMBED];
__device__ float g_rWv[(size_t)EMBED * EMBED];
__device__ float g_rWo[(size_t)EMBED * EMBED];

// ---------------------------------------------------------------------------
// Helpers (sm_103 base-target safe: cp.async + mma.sync, NO tcgen05)
// ---------------------------------------------------------------------------
__device__ __forceinline__ float round_tf32(float f) {
    uint32_t u;
    asm("cvt.rna.tf32.f32 %0, %1;" : "=r"(u) : "f"(f));
    return __uint_as_float(u);
}

__device__ __forceinline__ uint32_t smem_u32(const void* p) {
    uint32_t a;
    asm("{ .reg .u64 t; cvta.to.shared.u64 t, %1; cvt.u32.u64 %0, t; }"
        : "=r"(a) : "l"(p));
    return a;
}

__device__ __forceinline__ void cp16(uint32_t saddr, const void* gaddr) {
    asm volatile("cp.async.cg.shared.global [%0], [%1], 16;"
                 :: "r"(saddr), "l"(gaddr) : "memory");
}
#define CP_COMMIT() asm volatile("cp.async.commit_group;" ::: "memory")
#define CP_WAIT1()  asm volatile("cp.async.wait_group 1;" ::: "memory")

__device__ __forceinline__ void mma_tf32(float c[4],
    uint32_t a0, uint32_t a1, uint32_t a2, uint32_t a3,
    uint32_t b0, uint32_t b1)
{
    asm volatile(
        "mma.sync.aligned.m16n8k8.row.col.f32.tf32.tf32.f32 "
        "{%0,%1,%2,%3}, {%4,%5,%6,%7}, {%8,%9}, {%0,%1,%2,%3};"
        : "+f"(c[0]), "+f"(c[1]), "+f"(c[2]), "+f"(c[3])
        : "r"(a0), "r"(a1), "r"(a2), "r"(a3), "r"(b0), "r"(b1));
}

// ---------------------------------------------------------------------------
// Fragment-pack layouts (K is always EMBED=2048 here):
//  A-role (row-major src [R,2048]):
//    tile(rm,tk) = 16KB blob at (rm*64+tk)*4096 floats; within:
//    float4[(mt*4+kt)*32 + lane] = {S[m0][k0],S[m0+8][k0],S[m0][k0+4],S[m0+8][k0+4]}
//    m0 = rm*128+mt*16+(lane>>2), k0 = tk*32+kt*8+(lane&3)
//  B-role (row-major src [N,2048]):
//    tile(rn,tk) same blob size; within:
//    float2[(nt*4+kt)*32 + lane] = {S[n0][k0], S[n0][k0+4]}
//    n0 = rn*128+nt*8+(lane>>2), k0 = tk*32+kt*8+(lane&3)
// Both packs are tf32-rounded at write time (rna), so HW truncation is exact.
// ---------------------------------------------------------------------------

__global__ __launch_bounds__(256) void packA_round(
    const float4* __restrict__ s0, float4* __restrict__ d0,
    const float4* __restrict__ s1, float4* __restrict__ d1,
    const float4* __restrict__ s2, float4* __restrict__ d2, int total4)
{
    const int i = blockIdx.x * 256 + threadIdx.x;
    if (i >= total4) return;
    const float* s = (const float*)((blockIdx.z == 0) ? s0 : (blockIdx.z == 1) ? s1 : s2);
    float4*      d = (blockIdx.z == 0) ? d0 : (blockIdx.z == 1) ? d1 : d2;

    const int tile = i >> 10;            // 1024 float4 per 16KB tile
    const int w    = i & 1023;
    const int sub  = w >> 5;             // mt*4+kt
    const int lane = w & 31;
    const int mt = sub >> 2, kt = sub & 3;
    const int g  = lane >> 2, tq = lane & 3;
    const int rm = tile >> 6, tk = tile & 63;   // K/32 = 64
    const int m0 = rm * 128 + mt * 16 + g;
    const int k0 = tk * 32 + kt * 8 + tq;

    const float* p = s + (size_t)m0 * EMBED + k0;
    float4 o;
    o.x = round_tf32(p[0]);
    o.y = round_tf32(p[(size_t)8 * EMBED]);
    o.z = round_tf32(p[4]);
    o.w = round_tf32(p[(size_t)8 * EMBED + 4]);
    d[i] = o;
}

__global__ __launch_bounds__(256) void packB_round(
    const float* __restrict__ s0, float2* __restrict__ d0,
    const float* __restrict__ s1, float2* __restrict__ d1,
    const float* __restrict__ s2, float2* __restrict__ d2,
    const float* __restrict__ s3, float2* __restrict__ d3, int total2)
{
    const int i = blockIdx.x * 256 + threadIdx.x;
    if (i >= total2) return;
    const float* s; float2* d;
    switch (blockIdx.z) {
        case 0:  s = s0; d = d0; break;
        case 1:  s = s1; d = d1; break;
        case 2:  s = s2; d = d2; break;
        default: s = s3; d = d3; break;
    }
    const int tile = i >> 11;            // 2048 float2 per 16KB tile
    const int w    = i & 2047;
    const int sub  = w >> 5;             // nt*4+kt
    const int lane = w & 31;
    const int nt = sub >> 2, kt = sub & 3;
    const int g  = lane >> 2, tq = lane & 3;
    const int rn = tile >> 6, tk = tile & 63;
    const int n0 = rn * 128 + nt * 8 + g;
    const int k0 = tk * 32 + kt * 8 + tq;

    const float* p = s + (size_t)n0 * EMBED + k0;
    float2 o;
    o.x = round_tf32(p[0]);
    o.y = round_tf32(p[4]);
    d[i] = o;
}

// ---------------------------------------------------------------------------
// TF32 mma.sync GEMM mainloop on FRAGMENT-PACKED operands (shared body).
// 128x128 block tile, BK=32, 128 threads = 4 warps (2x2), warp tile 64x64.
// 3-stage cp.async pipeline + EXPLICIT double-buffered fragment registers:
// kt+1 fragments load (4x LDS.128 + 8x LDS.64) while kt's 32 HMMAs issue.
// ---------------------------------------------------------------------------
constexpr int NSTAGE  = 3;
constexpr int STAGE_B = 32768;                 // 16KB A + 16KB B
#define GEMM_SMEM_BYTES (NSTAGE * STAGE_B)     // 98304

__device__ __forceinline__ void load_frags(
    uint4 af[4], uint2 bf[8], const char* sa, const char* sb,
    int kt, int warp_m, int warp_n, int lane)
{
    #pragma unroll
    for (int i = 0; i < 4; i++) {
        const int mt = warp_m * 4 + i;
        af[i] = *(const uint4*)(sa + ((mt * 4 + kt) * 32 + lane) * 16);
    }
    #pragma unroll
    for (int j = 0; j < 8; j++) {
        const int nt = warp_n * 8 + j;
        bf[j] = *(const uint2*)(sb + ((nt * 4 + kt) * 32 + lane) * 8);
    }
}

__device__ __forceinline__ void mma_all(
    float acc[4][8][4], const uint4 af[4], const uint2 bf[8])
{
    #pragma unroll
    for (int i = 0; i < 4; i++)
        #pragma unroll
        for (int j = 0; j < 8; j++)
            mma_tf32(acc[i][j], af[i].x, af[i].y, af[i].z, af[i].w,
                     bf[j].x, bf[j].y);
}

__device__ __forceinline__ void gemm_body(
    const float* __restrict__ Ap, const float* __restrict__ Bp,
    const float* __restrict__ bias, float* __restrict__ C,
    int N, char* smem, int bx, int by)
{
    const uint32_t sbase = smem_u32(smem);
    const int tid    = threadIdx.x;
    const int lane   = tid & 31;
    const int wid    = tid >> 5;
    const int warp_m = wid >> 1;
    const int warp_n = wid & 1;

    const float* aBase = Ap + (size_t)by * KT64 * 4096;
    const float* bBase = Bp + (size_t)bx * KT64 * 4096;

    auto issue = [&](int stage, int ktile) {
        const uint32_t sa = sbase + stage * STAGE_B;
        const uint32_t sb = sa + 16384u;
        const float* aT = aBase + (size_t)ktile * 4096;
        const float* bT = bBase + (size_t)ktile * 4096;
        #pragma unroll
        for (int i = 0; i < 8; i++) {
            const int c = tid + 128 * i;
            cp16(sa + c * 16, aT + c * 4);
            cp16(sb + c * 16, bT + c * 4);
        }
        CP_COMMIT();
    };

    issue(0, 0);
    issue(1, 1);

    float acc[4][8][4];
    #pragma unroll
    for (int i = 0; i < 4; i++)
        #pragma unroll
        for (int j = 0; j < 8; j++)
            #pragma unroll
            for (int r = 0; r < 4; r++) acc[i][j][r] = 0.f;

    uint4 af0[4], af1[4];
    uint2 bf0[8], bf1[8];

    for (int t = 0; t < KT64; t++) {
        CP_WAIT1();
        __syncthreads();

        const char* sa = smem + (t % NSTAGE) * STAGE_B;
        const char* sb = sa + 16384;

        // prime kt=0 fragments, then issue the t+2 prefetch behind them
        load_frags(af0, bf0, sa, sb, 0, warp_m, warp_n, lane);
        if (t + 2 < KT64) issue((t + 2) % NSTAGE, t + 2);

        // kt pipeline: load kt+1 while kt's HMMAs occupy the tensor pipe
        load_frags(af1, bf1, sa, sb, 1, warp_m, warp_n, lane);
        mma_all(acc, af0, bf0);
        load_frags(af0, bf0, sa, sb, 2, warp_m, warp_n, lane);
        mma_all(acc, af1, bf1);
        load_frags(af1, bf1, sa, sb, 3, warp_m, warp_n, lane);
        mma_all(acc, af0, bf0);
        mma_all(acc, af1, bf1);
    }

    // Epilogue: fragment -> global (+ optional bias), float2 stores
    const int g  = lane >> 2;
    const int tq = lane & 3;
    const int bm = by * 128;
    const int bn = bx * 128;
    #pragma unroll
    for (int j = 0; j < 8; j++) {
        const int col = bn + warp_n * 64 + j * 8 + tq * 2;
        float b0 = 0.f, b1 = 0.f;
        if (bias) { b0 = bias[col]; b1 = bias[col + 1]; }
        #pragma unroll
        for (int i = 0; i < 4; i++) {
            const int row0 = bm + warp_m * 64 + i * 16 + g;
            float2 v01, v23;
            v01.x = acc[i][j][0] + b0; v01.y = acc[i][j][1] + b1;
            v23.x = acc[i][j][2] + b0; v23.y = acc[i][j][3] + b1;
            *(float2*)&C[(size_t)row0 * N + col]       = v01;
            *(float2*)&C[(size_t)(row0 + 8) * N + col] = v23;
        }
    }
}

// Batched Q/K/V projection GEMMs: one launch, blockIdx.z picks the triple.
// Continuous CTA supply lets wave-2+ work-stealing backfill across slices
// (one tail drain instead of three).
struct QkvArgs {
    const float* A[3];
    const float* B[3];
    float*       C[3];
};

__global__ __launch_bounds__(128, 2) void gemm_tf32_qkv(QkvArgs args)
{
    extern __shared__ __align__(128) char smem[];
    const int z = blockIdx.z;
    gemm_body(args.A[z], args.B[z], nullptr, args.C[z],
              EMBED, smem, blockIdx.x, blockIdx.y);
}

__global__ __launch_bounds__(128, 2) void gemm_tf32_nt(
    const float* __restrict__ Ap, const float* __restrict__ Bp,
    const float* __restrict__ bias, float* __restrict__ C, int N)
{
    extern __shared__ __align__(128) char smem[];
    gemm_body(Ap, Bp, bias, C, N, smem, blockIdx.x, blockIdx.y);
}

// ---------------------------------------------------------------------------
// Per-position head-mixing attention (einsum t,s index HEADS; h = sequence):
// per (b,l): E = Qr@Kr^T/sqrt(128) (16x16), row softmax, O = A@Vr (16x128).
// Output row-major + tf32-rounded (a packA pass re-packs it for the O-GEMM).
// ---------------------------------------------------------------------------
__global__ __launch_bounds__(256) void attn_kernel(
    const float* __restrict__ Q, const float* __restrict__ K,
    const float* __restrict__ V, float* __restrict__ O)
{
    __shared__ float q_s[16][132];
    __shared__ float k_s[16][132];
    __shared__ float v_s[16][132];
    __shared__ float e_s[16][17];

    const int row = blockIdx.x;
    const int tid = threadIdx.x;
    const size_t base = (size_t)row * EMBED;

    #pragma unroll
    for (int i = 0; i < 2; i++) {
        const int idx = tid + i * 256;
        const int h = idx >> 5;
        const int d = (idx & 31) * 4;
        const size_t gg = base + (size_t)h * HDIM + d;
        *(float4*)&q_s[h][d] = *(const float4*)(Q + gg);
        *(float4*)&k_s[h][d] = *(const float4*)(K + gg);
        *(float4*)&v_s[h][d] = *(const float4*)(V + gg);
    }
    __syncthreads();

    {
        const int ei = tid >> 4, ej = tid & 15;
        float e = 0.f;
        #pragma unroll
        for (int d = 0; d < HDIM; d++)
            e = fmaf(q_s[ei][d], k_s[ej][d], e);
        e_s[ei][ej] = e * 0.08838834764831845f;   // 1/sqrt(128)
    }
    __syncthreads();

    if (tid < 16) {
        float m = -3.4e38f;
        #pragma unroll
        for (int j = 0; j < 16; j++) m = fmaxf(m, e_s[tid][j]);
        float s = 0.f;
        #pragma unroll
        for (int j = 0; j < 16; j++) {
            float ex = expf(e_s[tid][j] - m);
            e_s[tid][j] = ex;
            s += ex;
        }
        const float inv = 1.f / s;
        #pragma unroll
        for (int j = 0; j < 16; j++) e_s[tid][j] *= inv;
    }
    __syncthreads();

    {
        const int d = tid & 127;
        const int gg = tid >> 7;
        #pragma unroll
        for (int ii = 0; ii < 8; ii++) {
            const int i = gg * 8 + ii;
            float acc = 0.f;
            #pragma unroll
            for (int s = 0; s < 16; s++)
                acc = fmaf(e_s[i][s], v_s[s][d], acc);
            O[base + (size_t)i * HDIM + d] = round_tf32(acc);
        }
    }
}

// ---------------------------------------------------------------------------
// kernel_launch (graph-capturable: kernel launches only)
// Input order (metadata): values, keys, queries, Wv, Wk, Wq, Wo, bo
// ---------------------------------------------------------------------------
extern "C" void kernel_launch(void* const* d_in, const int* in_sizes, int n_in,
                              void* d_out, int out_size)
{
    const float* values  = (const float*)d_in[0];
    const float* keys    = (const float*)d_in[1];
    const float* queries = (const float*)d_in[2];
    const float* Wv      = (const float*)d_in[3];
    const float* Wk      = (const float*)d_in[4];
    const float* Wq      = (const float*)d_in[5];
    const float* Wo      = (const float*)d_in[6];
    const float* bo      = (const float*)d_in[7];
    float* out = (float*)d_out;

    float *q, *k, *v, *attn, *attnp, *rq, *rk, *rv, *rWq, *rWk, *rWv, *rWo;
    cudaGetSymbolAddress((void**)&q,     g_q);
    cudaGetSymbolAddress((void**)&k,     g_k);
    cudaGetSymbolAddress((void**)&v,     g_v);
    cudaGetSymbolAddress((void**)&attn,  g_attn);
    cudaGetSymbolAddress((void**)&attnp, g_attnp);
    cudaGetSymbolAddress((void**)&rq,    g_rq);
    cudaGetSymbolAddress((void**)&rk,    g_rk);
    cudaGetSymbolAddress((void**)&rv,    g_rv);
    cudaGetSymbolAddress((void**)&rWq,   g_rWq);
    cudaGetSymbolAddress((void**)&rWk,   g_rWk);
    cudaGetSymbolAddress((void**)&rWv,   g_rWv);
    cudaGetSymbolAddress((void**)&rWo,   g_rWo);

    cudaFuncSetAttribute(gemm_tf32_qkv,
                         cudaFuncAttributeMaxDynamicSharedMemorySize,
                         GEMM_SMEM_BYTES);
    cudaFuncSetAttribute(gemm_tf32_nt,
                         cudaFuncAttributeMaxDynamicSharedMemorySize,
                         GEMM_SMEM_BYTES);

    const int nAct4 = (MROWS * EMBED) / 4;    // 2,097,152 float4
    const int nW2   = (EMBED * EMBED) / 2;    // 2,097,152 float2

    // Pack+round activations (A-role) and weights (B-role)
    {
        dim3 ga(nAct4 / 256, 1, 3);
        packA_round<<<ga, 256>>>(
            (const float4*)queries, (float4*)rq,
            (const float4*)keys,    (float4*)rk,
            (const float4*)values,  (float4*)rv, nAct4);
        dim3 gw(nW2 / 256, 1, 4);
        packB_round<<<gw, 256>>>(
            Wq, (float2*)rWq, Wk, (float2*)rWk,
            Wv, (float2*)rWv, Wo, (float2*)rWo, nW2);
    }

    // Q/K/V projections: single batched launch (grid.z = 3)
    {
        QkvArgs a;
        a.A[0] = rq;  a.B[0] = rWq; a.C[0] = q;
        a.A[1] = rk;  a.B[1] = rWk; a.C[1] = k;
        a.A[2] = rv;  a.B[2] = rWv; a.C[2] = v;
        dim3 grid(EMBED / 128, MROWS / 128, 3);   // (16, 32, 3)
        gemm_tf32_qkv<<<grid, 128, GEMM_SMEM_BYTES>>>(a);
    }

    attn_kernel<<<MROWS, 256>>>(q, k, v, attn);

    // Re-pack attn output as A-role operand for the output GEMM
    {
        dim3 gp(nAct4 / 256, 1, 1);
        packA_round<<<gp, 256>>>(
            (const float4*)attn, (float4*)attnp,
            (const float4*)attn, (float4*)attnp,
            (const float4*)attn, (float4*)attnp, nAct4);
    }

    {
        dim3 grid(EMBED / 128, MROWS / 128);      // (16, 32)
        gemm_tf32_nt<<<grid, 128, GEMM_SMEM_BYTES>>>(attnp, rWo, bo, out, EMBED);
    }
}